// round 2
// baseline (speedup 1.0000x reference)
#include <cuda_runtime.h>
#include <cstdint>

// ---------------- scratch (no allocations allowed; device globals) ----------------
__device__ float g_s1[1024 * 36 * 32 * 32];   // shared conv1 out (pooled)
__device__ float g_s2[1024 * 36 * 16 * 16];   // shared conv2 out (pooled)
__device__ float g_s3[1024 * 36 * 8 * 8];     // shared conv3 out (pooled)
__device__ float g_p1[1024 * 12 * 32 * 32];   // private conv out (pooled)
__device__ float g_x24[1024 * 24];            // concat [h | p]

// ---------------- packed fp32x2 helpers (Blackwell FFMA2) ----------------
__device__ __forceinline__ unsigned long long pk2(float lo, float hi) {
    unsigned long long r;
    asm("mov.b64 %0, {%1, %2};" : "=l"(r) : "f"(lo), "f"(hi));
    return r;
}
__device__ __forceinline__ unsigned long long ffma2(unsigned long long a,
                                                    unsigned long long b,
                                                    unsigned long long c) {
    unsigned long long d;
    asm("fma.rn.f32x2 %0, %1, %2, %3;" : "=l"(d) : "l"(a), "l"(b), "l"(c));
    return d;
}
__device__ __forceinline__ void upk2(unsigned long long v, float& lo, float& hi) {
    asm("mov.b64 {%0, %1}, %2;" : "=f"(lo), "=f"(hi) : "l"(v));
}

// ---------------- fused conv3x3(SAME) + activation + maxpool2, f32x2 math ----------------
// grid = (STRIPS, B). Block stages its input row-strip (+halo) in SMEM.
// Each thread computes a 2x2 pooled tile = 4x4 conv pixels from a 6x6 patch.
// Inner product uses packed fma.rn.f32x2 on column pairs: aligned pairs come free
// from the float4 LDS; only 2 cross pairs/row need mov.b64 packs.
// WSMEM=false -> weights read from global (warp-uniform oc => L1 broadcast).
template <int IC, int OC, int S, int STRIPS, bool WSMEM, bool LEAKY, bool USE_DOM, int NT>
__global__ void __launch_bounds__(NT)
convpool_kernel(const float* __restrict__ x,
                const float* __restrict__ Wbase,
                const float* __restrict__ Bbase,
                const int* __restrict__ dom_ptr,
                float* __restrict__ out)
{
    constexpr int RL  = S / STRIPS;   // conv rows handled per block
    constexpr int PH  = RL + 2;       // staged rows (with halo)
    constexpr int P   = S + 4;        // padded row stride (mult of 4 -> aligned float4)
    constexpr int HTY = RL / 4;       // 4x4 tile rows per strip
    constexpr int HTX = S / 4;
    constexpr int Sp  = S / 2;        // pooled output dim

    extern __shared__ float smem[];
    float* sx = smem;                       // IC * PH * P
    float* sw = smem + IC * PH * P;         // OC * IC * 9 (if WSMEM)

    const int strip = blockIdx.x;
    const int b     = blockIdx.y;
    const int tid   = threadIdx.x;

    int dom = 0;
    if (USE_DOM) dom = dom_ptr[0];
    const float* W  = Wbase + (size_t)dom * OC * IC * 9;
    const float* Bv = Bbase + (size_t)dom * OC;

    for (int i = tid; i < IC * PH * P; i += NT) sx[i] = 0.f;
    __syncthreads();

    const int r0   = strip * RL;
    const int gr0  = (r0 - 1 < 0) ? 0 : r0 - 1;
    const int gr1  = (r0 + RL + 1 > S) ? S : r0 + RL + 1;
    const int nrow = gr1 - gr0;
    const float* xb = x + (size_t)b * IC * S * S;
    for (int i = tid; i < IC * nrow * S; i += NT) {
        int c  = i / (nrow * S);
        int rr = (i / S) % nrow;
        int cc = i % S;
        int gr = gr0 + rr;
        sx[c * PH * P + (gr - r0 + 1) * P + (cc + 1)] = xb[c * S * S + gr * S + cc];
    }
    if (WSMEM)
        for (int i = tid; i < OC * IC * 9; i += NT) sw[i] = W[i];
    __syncthreads();

    constexpr int tilesPerOc = HTY * HTX;
    constexpr int tiles = OC * tilesPerOc;
    for (int t = tid; t < tiles; t += NT) {
        int oc  = t / tilesPerOc;
        int rem = t - oc * tilesPerOc;
        int ty  = rem / HTX;
        int tx  = rem - ty * HTX;

        unsigned long long accA[4], accB[4];   // (c0,c1) and (c2,c3) per out row
        #pragma unroll
        for (int i = 0; i < 4; i++) { accA[i] = 0ull; accB[i] = 0ull; }

        const float* wp    = WSMEM ? (sw + oc * IC * 9) : (W + oc * IC * 9);
        const float* xbase = sx + (4 * ty) * P + 4 * tx;

        for (int ci = 0; ci < IC; ci++) {
            unsigned long long Wd[9];
            #pragma unroll
            for (int k = 0; k < 9; k++) { float w = wp[k]; Wd[k] = pk2(w, w); }
            wp += 9;
            const float* xp = xbase + ci * PH * P;

            #pragma unroll
            for (int r = 0; r < 6; r++) {
                float4 a  = *reinterpret_cast<const float4*>(xp + r * P);
                float4 bq = *reinterpret_cast<const float4*>(xp + r * P + 4);
                unsigned long long q01 = pk2(a.x, a.y);
                unsigned long long q12 = pk2(a.y, a.z);
                unsigned long long q23 = pk2(a.z, a.w);
                unsigned long long q34 = pk2(a.w, bq.x);
                unsigned long long q45 = pk2(bq.x, bq.y);
                #pragma unroll
                for (int orow = 0; orow < 4; orow++) {
                    int j = r - orow;           // tap row
                    if (j >= 0 && j < 3) {
                        accA[orow] = ffma2(Wd[3*j],     q01, accA[orow]);
                        accA[orow] = ffma2(Wd[3*j + 1], q12, accA[orow]);
                        accA[orow] = ffma2(Wd[3*j + 2], q23, accA[orow]);
                        accB[orow] = ffma2(Wd[3*j],     q23, accB[orow]);
                        accB[orow] = ffma2(Wd[3*j + 1], q34, accB[orow]);
                        accB[orow] = ffma2(Wd[3*j + 2], q45, accB[orow]);
                    }
                }
            }
        }

        // unpack, pool(max), bias, activation (act(max+b) == pool(act(.+b)), monotonic)
        float v[4][4];
        #pragma unroll
        for (int r = 0; r < 4; r++) {
            upk2(accA[r], v[r][0], v[r][1]);
            upk2(accB[r], v[r][2], v[r][3]);
        }
        float bias = WSMEM ? Bv[oc] : __ldg(Bv + oc);
        int prow0 = strip * (RL / 2) + 2 * ty;
        float* ob = out + (((size_t)b * OC + oc) * Sp + prow0) * Sp + 2 * tx;
        #pragma unroll
        for (int pr = 0; pr < 2; pr++) {
            #pragma unroll
            for (int pc = 0; pc < 2; pc++) {
                float m = fmaxf(fmaxf(v[2*pr][2*pc],   v[2*pr][2*pc+1]),
                                fmaxf(v[2*pr+1][2*pc], v[2*pr+1][2*pc+1]));
                m += bias;
                float o;
                if (LEAKY) o = (m > 0.f) ? m : 0.001f * m;
                else       o = fmaxf(m, 0.f);
                ob[pr * Sp + pc] = o;
            }
        }
    }
}

// ---------------- FC: [B,K] @ W[12,K]^T + b -> write into concat buffer ----------------
template <int K, bool RELU, bool USE_DOM>
__global__ void fc12_kernel(const float* __restrict__ x,
                            const float* __restrict__ Wbase,
                            const float* __restrict__ Bbase,
                            const int* __restrict__ dom_ptr,
                            float* __restrict__ out, int out_off)
{
    const int warp = threadIdx.x >> 5;
    const int lane = threadIdx.x & 31;
    const int b = blockIdx.x * 8 + warp;
    int dom = 0;
    if (USE_DOM) dom = dom_ptr[0];
    const float* W = Wbase + (size_t)dom * 12 * K;
    const float4* xr = reinterpret_cast<const float4*>(x + (size_t)b * K);

    float4 acc[12];
    #pragma unroll
    for (int j = 0; j < 12; j++) acc[j] = make_float4(0.f, 0.f, 0.f, 0.f);

    for (int k4 = lane; k4 < K / 4; k4 += 32) {
        float4 xv = xr[k4];
        #pragma unroll
        for (int j = 0; j < 12; j++) {
            float4 wv = reinterpret_cast<const float4*>(W + (size_t)j * K)[k4];
            acc[j].x = fmaf(xv.x, wv.x, acc[j].x);
            acc[j].y = fmaf(xv.y, wv.y, acc[j].y);
            acc[j].z = fmaf(xv.z, wv.z, acc[j].z);
            acc[j].w = fmaf(xv.w, wv.w, acc[j].w);
        }
    }
    const float* Bv = Bbase + dom * 12;
    #pragma unroll
    for (int j = 0; j < 12; j++) {
        float s = (acc[j].x + acc[j].y) + (acc[j].z + acc[j].w);
        #pragma unroll
        for (int o = 16; o > 0; o >>= 1) s += __shfl_xor_sync(0xffffffffu, s, o);
        if (lane == j) {
            float v2 = s + Bv[j];
            if (RELU) v2 = fmaxf(v2, 0.f);
            out[b * 24 + out_off + j] = v2;
        }
    }
}

// ---------------- per-sample task-routed heads: 24 -> 28 -> 14 -> 5 ----------------
__global__ void heads_kernel(const float* __restrict__ x24,
                             const int* __restrict__ tt,
                             const float* __restrict__ W1, const float* __restrict__ b1,
                             const float* __restrict__ W2, const float* __restrict__ b2,
                             const float* __restrict__ W3, const float* __restrict__ b3,
                             float* __restrict__ out)
{
    const int warp = threadIdx.x >> 5;
    const int lane = threadIdx.x & 31;
    const int b = blockIdx.x * 8 + warp;
    const int t = tt[b];

    float xv = (lane < 24) ? x24[b * 24 + lane] : 0.f;

    const float* w1 = W1 + t * 28 * 24 + min(lane, 27) * 24;
    float h1 = 0.f;
    #pragma unroll
    for (int k = 0; k < 24; k++)
        h1 = fmaf(w1[k], __shfl_sync(0xffffffffu, xv, k), h1);
    if (lane < 28) h1 += b1[t * 28 + lane];
    h1 = fmaxf(h1, 0.f);
    if (lane >= 28) h1 = 0.f;

    const float* w2 = W2 + t * 14 * 28 + min(lane, 13) * 28;
    float h2 = 0.f;
    #pragma unroll
    for (int k = 0; k < 28; k++)
        h2 = fmaf(w2[k], __shfl_sync(0xffffffffu, h1, k), h2);
    if (lane < 14) h2 += b2[t * 14 + lane];
    h2 = fmaxf(h2, 0.f);
    if (lane >= 14) h2 = 0.f;

    const float* w3 = W3 + t * 5 * 14 + min(lane, 4) * 14;
    float o = 0.f;
    #pragma unroll
    for (int k = 0; k < 14; k++)
        o = fmaf(w3[k], __shfl_sync(0xffffffffu, h2, k), o);
    if (lane < 5) out[b * 5 + lane] = o + b3[t * 5 + lane];
}

// ---------------- launch ----------------
extern "C" void kernel_launch(void* const* d_in, const int* in_sizes, int n_in,
                              void* d_out, int out_size)
{
    const float* x_s = (const float*)d_in[0];
    const float* x_p = (const float*)d_in[1];
    const int*   tt  = (const int*)d_in[2];
    const int*   dom = (const int*)d_in[3];
    const float* WsW = (const float*)d_in[4];
    const float* Wsb = (const float*)d_in[5];
    const float* WhW = (const float*)d_in[6];
    const float* Whb = (const float*)d_in[7];
    const float* WfW = (const float*)d_in[8];
    const float* Wfb = (const float*)d_in[9];
    const float* PcW = (const float*)d_in[10];
    const float* Pcb = (const float*)d_in[11];
    const float* PlW = (const float*)d_in[12];
    const float* Plb = (const float*)d_in[13];
    const float* H1W = (const float*)d_in[14];
    const float* H1b = (const float*)d_in[15];
    const float* H2W = (const float*)d_in[16];
    const float* H2b = (const float*)d_in[17];
    const float* H3W = (const float*)d_in[18];
    const float* H3b = (const float*)d_in[19];
    float* out = (float*)d_out;
    const int B = in_sizes[2];  // 1024

    float *s1, *s2, *s3, *p1, *x24;
    cudaGetSymbolAddress((void**)&s1,  g_s1);
    cudaGetSymbolAddress((void**)&s2,  g_s2);
    cudaGetSymbolAddress((void**)&s3,  g_s3);
    cudaGetSymbolAddress((void**)&p1,  g_p1);
    cudaGetSymbolAddress((void**)&x24, g_x24);

    // conv1: whole image + weights in smem
    const size_t sm1 = (size_t)(3 * 66 * 68 + 36 * 3 * 9)   * sizeof(float); //  57.7 KB
    // conv2: 2 row strips, weights via uniform LDG (no smem) -> 2 blocks/SM
    const size_t sm2 = (size_t)(36 * 18 * 36)               * sizeof(float); //  93.3 KB
    // conv3: whole image + weights in smem
    const size_t sm3 = (size_t)(36 * 18 * 20 + 36 * 36 * 9) * sizeof(float); //  98.5 KB
    // private conv
    const size_t smp = (size_t)(3 * 66 * 68 + 12 * 3 * 9)   * sizeof(float); //  55.2 KB

    cudaFuncSetAttribute(convpool_kernel<3, 36, 64, 1, true,  false, false, 256>,
                         cudaFuncAttributeMaxDynamicSharedMemorySize, (int)sm1);
    cudaFuncSetAttribute(convpool_kernel<36, 36, 32, 2, false, false, false, 288>,
                         cudaFuncAttributeMaxDynamicSharedMemorySize, (int)sm2);
    cudaFuncSetAttribute(convpool_kernel<36, 36, 16, 1, true,  false, false, 288>,
                         cudaFuncAttributeMaxDynamicSharedMemorySize, (int)sm3);
    cudaFuncSetAttribute(convpool_kernel<3, 12, 64, 1, true,  true,  true, 256>,
                         cudaFuncAttributeMaxDynamicSharedMemorySize, (int)smp);

    // shared branch
    convpool_kernel<3, 36, 64, 1, true, false, false, 256>
        <<<dim3(1, B), 256, sm1>>>(x_s, WsW, Wsb, nullptr, s1);
    convpool_kernel<36, 36, 32, 2, false, false, false, 288>
        <<<dim3(2, B), 288, sm2>>>(s1, WhW, Whb, nullptr, s2);
    convpool_kernel<36, 36, 16, 1, true, false, false, 288>
        <<<dim3(1, B), 288, sm3>>>(s2, WhW, Whb, nullptr, s3);
    // private branch
    convpool_kernel<3, 12, 64, 1, true, true, true, 256>
        <<<dim3(1, B), 256, smp>>>(x_p, PcW, Pcb, dom, p1);
    // FCs -> concat buffer
    fc12_kernel<2304,  true,  false><<<B / 8, 256>>>(s3, WfW, Wfb, nullptr, x24, 0);
    fc12_kernel<12288, false, true ><<<B / 8, 256>>>(p1, PlW, Plb, dom,     x24, 12);
    // routed heads -> output
    heads_kernel<<<B / 8, 256>>>(x24, tt, H1W, H1b, H2W, H2b, H3W, H3b, out);
}